// round 3
// baseline (speedup 1.0000x reference)
#include <cuda_runtime.h>
#include <cstdint>
#include <math.h>

// ---------------- problem constants ----------------
#define NROWS   65536
#define SDIM    256
#define ADIM    129
#define HID     256
#define NSTEP   30
#define EPS_LN  1e-5f

#define TM      32      // rows per CTA
#define RPW     8       // rows per warp (4 warps * 8 = 32)
#define XSTR    132     // padded float stride for x rows (16B-aligned, zero pad 129..131)

typedef unsigned long long u64;

// packed fp32x2 helpers (sm_103a FFMA2)
__device__ __forceinline__ u64 pk2(float lo, float hi) {
    u64 r; asm("mov.b64 %0,{%1,%2};" : "=l"(r) : "f"(lo), "f"(hi)); return r;
}
__device__ __forceinline__ float2 up2(u64 v) {
    float lo, hi; asm("mov.b64 {%0,%1},%2;" : "=f"(lo), "=f"(hi) : "l"(v));
    float2 f; f.x = lo; f.y = hi; return f;
}
__device__ __forceinline__ void fma2(u64 &d, u64 a, u64 b) {
    asm("fma.rn.f32x2 %0,%1,%2,%0;" : "+l"(d) : "l"(a), "l"(b));
}

// W1 x-part (rows 256..384) zero-padded to 132 k-rows, stride 256
__device__ float g_W1xp[132 * HID];
// W3 zero-padded to 132 cols, stride 132
__device__ float g_W3p[HID * 132];

__global__ void pack_w1x_kernel(const float* __restrict__ W1) {
    int i = blockIdx.x * blockDim.x + threadIdx.x;
    if (i < 132 * HID) {
        int k = i / HID, c = i - k * HID;
        g_W1xp[i] = (k < 129) ? W1[(size_t)(SDIM + k) * HID + c] : 0.0f;
    }
}
__global__ void pack_w3_kernel(const float* __restrict__ W3) {
    int i = blockIdx.x * blockDim.x + threadIdx.x;
    if (i < HID * 132) {
        int k = i / 132, c = i - k * 132;
        g_W3p[i] = (c < ADIM) ? W3[k * ADIM + c] : 0.0f;
    }
}

// ---- load one 4-k block of weights (256-wide row): 8 float4 per lane ----
__device__ __forceinline__ void loadw(float4 w[8], const float* __restrict__ Wg,
                                      int jb, int c0, int c1) {
    const float* p = Wg + (size_t)jb * 4 * HID;
    #pragma unroll
    for (int j = 0; j < 4; j++) {
        w[2*j]   = *(const float4*)(p + j * HID + c0);
        w[2*j+1] = *(const float4*)(p + j * HID + c1);
    }
}

// ---- FMA one 4-k block over 8 rows, 8 cols/lane ----
__device__ __forceinline__ void fmablock(const float4 w[8], const float* __restrict__ src,
                                         int sstr, int jb, u64 acc[RPW][4]) {
    float4 av[RPW];
    #pragma unroll
    for (int i = 0; i < RPW; i++)
        av[i] = *(const float4*)(src + i * sstr + jb * 4);
    #pragma unroll
    for (int j = 0; j < 4; j++) {
        const u64 w0 = pk2(w[2*j].x,   w[2*j].y);
        const u64 w1 = pk2(w[2*j].z,   w[2*j].w);
        const u64 w2 = pk2(w[2*j+1].x, w[2*j+1].y);
        const u64 w3 = pk2(w[2*j+1].z, w[2*j+1].w);
        #pragma unroll
        for (int i = 0; i < RPW; i++) {
            const float v = (j == 0) ? av[i].x : (j == 1) ? av[i].y
                          : (j == 2) ? av[i].z : av[i].w;
            const u64 xv = pk2(v, v);
            fma2(acc[i][0], w0, xv);
            fma2(acc[i][1], w1, xv);
            fma2(acc[i][2], w2, xv);
            fma2(acc[i][3], w3, xv);
        }
    }
}

// ---- K-loop GEMM with register ping-pong weight prefetch ----
template<int KB>
__device__ __forceinline__ void gemm8(const float* __restrict__ Wg,
                                      const float* __restrict__ src, int sstr,
                                      u64 acc[RPW][4], int c0, int c1)
{
    float4 wA[8], wB[8];
    loadw(wA, Wg, 0, c0, c1);
    #pragma unroll 1
    for (int jb = 0; jb < KB; jb += 2) {
        if (jb + 1 < KB) loadw(wB, Wg, jb + 1, c0, c1);
        fmablock(wA, src, sstr, jb, acc);
        if (jb + 1 < KB) {
            if (jb + 2 < KB) loadw(wA, Wg, jb + 2, c0, c1);
            fmablock(wB, src, sstr, jb + 1, acc);
        }
    }
}

// ---- layer-3 variant: 4 cols/lane, weights from g_W3p (stride 132) ----
__device__ __forceinline__ void loadw3(float4 w[4], int jb, int c0) {
    #pragma unroll
    for (int j = 0; j < 4; j++)
        w[j] = *(const float4*)(g_W3p + (size_t)(jb * 4 + j) * 132 + c0);
}
__device__ __forceinline__ void fmablock3(const float4 w[4], const float* __restrict__ src,
                                          int jb, u64 acc[RPW][2]) {
    float4 av[RPW];
    #pragma unroll
    for (int i = 0; i < RPW; i++)
        av[i] = *(const float4*)(src + i * HID + jb * 4);
    #pragma unroll
    for (int j = 0; j < 4; j++) {
        const u64 w0 = pk2(w[j].x, w[j].y);
        const u64 w1 = pk2(w[j].z, w[j].w);
        #pragma unroll
        for (int i = 0; i < RPW; i++) {
            const float v = (j == 0) ? av[i].x : (j == 1) ? av[i].y
                          : (j == 2) ? av[i].z : av[i].w;
            const u64 xv = pk2(v, v);
            fma2(acc[i][0], w0, xv);
            fma2(acc[i][1], w1, xv);
        }
    }
}

// LayerNorm (two-pass) + ReLU + store to smem (stride 256)
__device__ __forceinline__ void ln_relu_store(u64 acc[RPW][4], float* __restrict__ dst,
                                              const float* __restrict__ g,
                                              const float* __restrict__ be,
                                              int c0, int c1)
{
    const float4 ga = *(const float4*)(g + c0);
    const float4 gb = *(const float4*)(g + c1);
    const float4 ba = *(const float4*)(be + c0);
    const float4 bb = *(const float4*)(be + c1);
    #pragma unroll
    for (int i = 0; i < RPW; i++) {
        float2 a0 = up2(acc[i][0]), a1 = up2(acc[i][1]);
        float2 a2 = up2(acc[i][2]), a3 = up2(acc[i][3]);
        float s = ((a0.x + a0.y) + (a1.x + a1.y)) + ((a2.x + a2.y) + (a3.x + a3.y));
        #pragma unroll
        for (int o = 16; o > 0; o >>= 1) s += __shfl_xor_sync(0xffffffffu, s, o);
        const float m = s * (1.0f / 256.0f);
        const float d0 = a0.x - m, d1 = a0.y - m, d2 = a1.x - m, d3 = a1.y - m;
        const float d4 = a2.x - m, d5 = a2.y - m, d6 = a3.x - m, d7 = a3.y - m;
        float ss = ((d0*d0 + d1*d1) + (d2*d2 + d3*d3)) + ((d4*d4 + d5*d5) + (d6*d6 + d7*d7));
        #pragma unroll
        for (int o = 16; o > 0; o >>= 1) ss += __shfl_xor_sync(0xffffffffu, ss, o);
        const float inv = rsqrtf(ss * (1.0f / 256.0f) + EPS_LN);
        float4 h0, h1;
        h0.x = fmaxf(d0 * inv * ga.x + ba.x, 0.0f);
        h0.y = fmaxf(d1 * inv * ga.y + ba.y, 0.0f);
        h0.z = fmaxf(d2 * inv * ga.z + ba.z, 0.0f);
        h0.w = fmaxf(d3 * inv * ga.w + ba.w, 0.0f);
        h1.x = fmaxf(d4 * inv * gb.x + bb.x, 0.0f);
        h1.y = fmaxf(d5 * inv * gb.y + bb.y, 0.0f);
        h1.z = fmaxf(d6 * inv * gb.z + bb.z, 0.0f);
        h1.w = fmaxf(d7 * inv * gb.w + bb.w, 0.0f);
        *(float4*)(dst + i * HID + c0) = h0;
        *(float4*)(dst + i * HID + c1) = h1;
    }
}

// Occupancy-1 by smem: 116 KB/CTA means two CTAs (232 KB) cannot co-reside
// within the 228 KB carveout -> exactly 1 warp per SMSP -> FFMA2 issue slots
// (256 per 256-cyc FMA window) exceed per-warp demand (~192) -> FMA-bound.
#define SMEM_PAD_FLOATS 29696                    // 118784 bytes
#define SMEM_BYTES (SMEM_PAD_FLOATS * sizeof(float))

__global__ void __launch_bounds__(128, 1)
actor_kernel(const float* __restrict__ state,  const float* __restrict__ amask,
             const float* __restrict__ x_init, const float* __restrict__ gumbel,
             const float* __restrict__ W1,     const float* __restrict__ b1,
             const float* __restrict__ g1,     const float* __restrict__ be1,
             const float* __restrict__ W2,     const float* __restrict__ b2,
             const float* __restrict__ g2,     const float* __restrict__ be2,
             const float* __restrict__ b3,     float* __restrict__ out)
{
    extern __shared__ float sm[];
    float* s1 = sm;                    // [TM][256] state@W1a + b1 (step-invariant)
    float* hb = sm + TM * HID;         // [TM][256] h buffer
    float* xs = sm + 2 * TM * HID;     // [TM][132] x (129 live + zero pad)

    const int lane  = threadIdx.x & 31;
    const int wid   = threadIdx.x >> 5;
    const int rbase = wid * RPW;
    const size_t grow0 = (size_t)blockIdx.x * TM;
    const int c0 = lane * 4;
    const int c1 = 128 + lane * 4;

    float* xw  = xs + rbase * XSTR;    // warp's x rows
    float* hw  = hb + rbase * HID;     // warp's h rows
    float* s1w = s1 + rbase * HID;

    // ---- load x rows (stride 129, scalar coalesced) + zero pads ----
    #pragma unroll
    for (int i = 0; i < RPW; i++) {
        const size_t gr = grow0 + rbase + i;
        const float* xp = x_init + gr * ADIM;
        #pragma unroll
        for (int j = 0; j < 4; j++) xw[i * XSTR + lane + 32 * j] = xp[lane + 32 * j];
        if (lane == 0) xw[i * XSTR + 128] = xp[128];
        if (lane >= 1 && lane <= 3) xw[i * XSTR + 128 + lane] = 0.0f;
    }
    // ---- stage state rows in hb ----
    #pragma unroll
    for (int i = 0; i < RPW; i++) {
        const float* sp = state + (grow0 + rbase + i) * SDIM;
        *(float4*)(hw + i * HID + c0) = *(const float4*)(sp + c0);
        *(float4*)(hw + i * HID + c1) = *(const float4*)(sp + c1);
    }
    __syncwarp();

    // step-invariant preloads
    float w128[8];  // W3 col 128, lane-strided over k
    #pragma unroll
    for (int j = 0; j < 8; j++) w128[j] = g_W3p[(size_t)(lane + 32 * j) * 132 + 128];
    const float b3L = __ldg(b3 + 128);

    u64 acc[RPW][4];

    // ---- S1 = state @ W1[0:256,:] + b1 (hoisted) ----
    {
        const float4 ba = *(const float4*)(b1 + c0);
        const float4 bb = *(const float4*)(b1 + c1);
        #pragma unroll
        for (int i = 0; i < RPW; i++) {
            acc[i][0] = pk2(ba.x, ba.y); acc[i][1] = pk2(ba.z, ba.w);
            acc[i][2] = pk2(bb.x, bb.y); acc[i][3] = pk2(bb.z, bb.w);
        }
        gemm8<64>(W1, hw, HID, acc, c0, c1);
        #pragma unroll
        for (int i = 0; i < RPW; i++) {
            float2 a0 = up2(acc[i][0]), a1 = up2(acc[i][1]);
            float2 a2 = up2(acc[i][2]), a3 = up2(acc[i][3]);
            float4 v0; v0.x = a0.x; v0.y = a0.y; v0.z = a1.x; v0.w = a1.y;
            float4 v1; v1.x = a2.x; v1.y = a2.y; v1.z = a3.x; v1.w = a3.y;
            *(float4*)(s1w + i * HID + c0) = v0;
            *(float4*)(s1w + i * HID + c1) = v1;
        }
    }
    __syncwarp();

    // ---- 30 diffusion steps (warp-private, no __syncthreads) ----
    for (int s = 0; s < NSTEP; s++) {
        const float t = (float)(NSTEP - 1 - s);

        // layer 1: acc = S1 + t*W1[385]; += x @ W1x (K=132 padded); LN+ReLU -> hb
        {
            const float4 wa = *(const float4*)(W1 + (size_t)385 * HID + c0);
            const float4 wb = *(const float4*)(W1 + (size_t)385 * HID + c1);
            #pragma unroll
            for (int i = 0; i < RPW; i++) {
                const float4 sa = *(const float4*)(s1w + i * HID + c0);
                const float4 sb = *(const float4*)(s1w + i * HID + c1);
                acc[i][0] = pk2(fmaf(t, wa.x, sa.x), fmaf(t, wa.y, sa.y));
                acc[i][1] = pk2(fmaf(t, wa.z, sa.z), fmaf(t, wa.w, sa.w));
                acc[i][2] = pk2(fmaf(t, wb.x, sb.x), fmaf(t, wb.y, sb.y));
                acc[i][3] = pk2(fmaf(t, wb.z, sb.z), fmaf(t, wb.w, sb.w));
            }
            gemm8<33>(g_W1xp, xw, XSTR, acc, c0, c1);
            ln_relu_store(acc, hw, g1, be1, c0, c1);
        }
        __syncwarp();

        // layer 2: acc = b2; += h1 @ W2; LN+ReLU -> hb
        {
            const float4 ba = *(const float4*)(b2 + c0);
            const float4 bb = *(const float4*)(b2 + c1);
            #pragma unroll
            for (int i = 0; i < RPW; i++) {
                acc[i][0] = pk2(ba.x, ba.y); acc[i][1] = pk2(ba.z, ba.w);
                acc[i][2] = pk2(bb.x, bb.y); acc[i][3] = pk2(bb.z, bb.w);
            }
            gemm8<64>(W2, hw, HID, acc, c0, c1);
            __syncwarp();                      // WAR: all lanes done reading hb
            ln_relu_store(acc, hw, g2, be2, c0, c1);
        }
        __syncwarp();

        // layer 3: noise = h2 @ W3 + b3; x -= 0.1*noise
        {
            u64 a3[RPW][2];
            const float4 b3v = *(const float4*)(b3 + c0);
            #pragma unroll
            for (int i = 0; i < RPW; i++) {
                a3[i][0] = pk2(b3v.x, b3v.y);
                a3[i][1] = pk2(b3v.z, b3v.w);
            }
            // main 128 cols (4 per lane), ping-pong prefetch
            {
                float4 wA[4], wB[4];
                loadw3(wA, 0, c0);
                #pragma unroll 1
                for (int jb = 0; jb < 64; jb += 2) {
                    loadw3(wB, jb + 1, c0);
                    fmablock3(wA, hw, jb, a3);
                    if (jb + 2 < 64) loadw3(wA, jb + 2, c0);
                    fmablock3(wB, hw, jb + 1, a3);
                }
            }
            // col 128: lane-strided partial dot + butterfly reduce per row
            float a128[RPW];
            #pragma unroll
            for (int i = 0; i < RPW; i++) a128[i] = 0.0f;
            #pragma unroll
            for (int j = 0; j < 8; j++) {
                #pragma unroll
                for (int i = 0; i < RPW; i++) {
                    const float hv = hw[i * HID + lane + 32 * j];
                    a128[i] = fmaf(hv, w128[j], a128[i]);
                }
            }
            #pragma unroll
            for (int i = 0; i < RPW; i++) {
                #pragma unroll
                for (int o = 16; o > 0; o >>= 1)
                    a128[i] += __shfl_xor_sync(0xffffffffu, a128[i], o);
            }
            // x update
            #pragma unroll
            for (int i = 0; i < RPW; i++) {
                float4 xo = *(float4*)(xw + i * XSTR + c0);
                const float2 n0 = up2(a3[i][0]), n1 = up2(a3[i][1]);
                xo.x -= 0.1f * n0.x;
                xo.y -= 0.1f * n0.y;
                xo.z -= 0.1f * n1.x;
                xo.w -= 0.1f * n1.y;
                *(float4*)(xw + i * XSTR + c0) = xo;
                if (lane == 0)
                    xw[i * XSTR + 128] -= 0.1f * (b3L + a128[i]);
            }
        }
        __syncwarp();
    }

    // ---- epilogue: masked gumbel softmax argmax (straight-through) + tanh ----
    #pragma unroll
    for (int i = 0; i < RPW; i++) {
        const size_t gr = grow0 + rbase + i;
        const float4 xv = *(const float4*)(xw + i * XSTR + c0);
        const float4 mk = *(const float4*)(amask  + gr * 128 + c0);
        const float4 gn = *(const float4*)(gumbel + gr * 128 + c0);
        float z[4];
        z[0] = xv.x + (1.0f - mk.x) * (-1e9f) + gn.x;
        z[1] = xv.y + (1.0f - mk.y) * (-1e9f) + gn.y;
        z[2] = xv.z + (1.0f - mk.z) * (-1e9f) + gn.z;
        z[3] = xv.w + (1.0f - mk.w) * (-1e9f) + gn.w;
        float best = z[0]; int bi = c0;
        #pragma unroll
        for (int j = 1; j < 4; j++) if (z[j] > best) { best = z[j]; bi = c0 + j; }
        #pragma unroll
        for (int o = 16; o > 0; o >>= 1) {
            float ov = __shfl_xor_sync(0xffffffffu, best, o);
            int   oi = __shfl_xor_sync(0xffffffffu, bi,   o);
            if (ov > best || (ov == best && oi < bi)) { best = ov; bi = oi; }
        }
        float e[4]; float sl = 0.0f;
        #pragma unroll
        for (int j = 0; j < 4; j++) { e[j] = expf(z[j] - best); sl += e[j]; }
        #pragma unroll
        for (int o = 16; o > 0; o >>= 1) sl += __shfl_xor_sync(0xffffffffu, sl, o);
        #pragma unroll
        for (int j = 0; j < 4; j++) {
            const float p  = e[j] / sl;
            const float yh = (c0 + j == bi) ? 1.0f : 0.0f;
            const float tv = yh + p;
            out[gr * ADIM + c0 + j] = tv - p;
        }
        if (lane == 0) out[gr * ADIM + 128] = tanhf(xw[i * XSTR + 128]);
    }
}

extern "C" void kernel_launch(void* const* d_in, const int* in_sizes, int n_in,
                              void* d_out, int out_size)
{
    const float* state  = (const float*)d_in[0];
    const float* amask  = (const float*)d_in[1];
    const float* x_init = (const float*)d_in[2];
    const float* gumbel = (const float*)d_in[3];
    const float* W1     = (const float*)d_in[4];
    const float* b1     = (const float*)d_in[5];
    const float* g1     = (const float*)d_in[6];
    const float* be1    = (const float*)d_in[7];
    const float* W2     = (const float*)d_in[8];
    const float* b2     = (const float*)d_in[9];
    const float* g2     = (const float*)d_in[10];
    const float* be2    = (const float*)d_in[11];
    const float* W3     = (const float*)d_in[12];
    const float* b3     = (const float*)d_in[13];
    float* out          = (float*)d_out;

    pack_w1x_kernel<<<(132 * HID + 255) / 256, 256>>>(W1);
    pack_w3_kernel<<<(HID * 132 + 255) / 256, 256>>>(W3);

    cudaFuncSetAttribute(actor_kernel,
                         cudaFuncAttributeMaxDynamicSharedMemorySize,
                         (int)SMEM_BYTES);

    actor_kernel<<<NROWS / TM, 128, SMEM_BYTES>>>(
        state, amask, x_init, gumbel,
        W1, b1, g1, be1, W2, b2, g2, be2, b3, out);
}

// round 5
// speedup vs baseline: 1.2706x; 1.2706x over previous
#include <cuda_runtime.h>
#include <cstdint>
#include <math.h>

// ---------------- problem constants ----------------
#define NROWS   65536
#define SDIM    256
#define ADIM    129
#define HID     256
#define NSTEP   30
#define EPS_LN  1e-5f

#define TM      32      // rows per CTA
#define RPW     8       // rows per warp (4 warps * 8 = 32)
#define XSTR    132     // padded float stride for x rows
#define HDSTR   512     // duplicated h stride (each value stored twice)

typedef unsigned long long u64;

// packed fp32x2 helpers (sm_103a FFMA2)
__device__ __forceinline__ u64 pk2(float lo, float hi) {
    u64 r; asm("mov.b64 %0,{%1,%2};" : "=l"(r) : "f"(lo), "f"(hi)); return r;
}
__device__ __forceinline__ float2 up2(u64 v) {
    float lo, hi; asm("mov.b64 {%0,%1},%2;" : "=f"(lo), "=f"(hi) : "l"(v));
    float2 f; f.x = lo; f.y = hi; return f;
}
__device__ __forceinline__ void fma2(u64 &d, u64 a, u64 b) {
    asm("fma.rn.f32x2 %0,%1,%2,%0;" : "+l"(d) : "l"(a), "l"(b));
}

// W1 x-part (rows 256..384) zero-padded to 132 k-rows, stride 256
__device__ float g_W1xp[132 * HID];
// W3 zero-padded to 132 cols, stride 132
__device__ float g_W3p[HID * 132];

// single pack kernel -> launch order [pack, actor] so ncu -s 5 samples actor
__global__ void pack_kernel(const float* __restrict__ W1, const float* __restrict__ W3) {
    int i = blockIdx.x * blockDim.x + threadIdx.x;
    if (i < 132 * HID) {
        int k = i / HID, c = i - k * HID;
        g_W1xp[i] = (k < 129) ? W1[(size_t)(SDIM + k) * HID + c] : 0.0f;
    }
    if (i < HID * 132) {
        int k = i / 132, c = i - k * 132;
        g_W3p[i] = (c < ADIM) ? W3[k * ADIM + c] : 0.0f;
    }
}

// ---- weights: one 4-k block of a 256-wide row as aligned u64 halves (no movs) ----
__device__ __forceinline__ void loadw_u64(u64 w[16], const float* __restrict__ Wg,
                                          int jb, int c0, int c1) {
    #pragma unroll
    for (int j = 0; j < 4; j++) {
        const float* p = Wg + (size_t)(jb * 4 + j) * HID;
        const ulonglong2 a = *(const ulonglong2*)(p + c0);
        const ulonglong2 b = *(const ulonglong2*)(p + c1);
        w[4*j+0] = a.x; w[4*j+1] = a.y; w[4*j+2] = b.x; w[4*j+3] = b.y;
    }
}

// ---- FMA one 4-k block; activations read duplicated ((v,v) pairs, no movs) ----
__device__ __forceinline__ void fmablock_dup(const u64 w[16], const float* __restrict__ srcd,
                                             int jb, u64 acc[RPW][4]) {
    u64 av[RPW][2];
    #pragma unroll
    for (int i = 0; i < RPW; i++) {
        const ulonglong2 p = *(const ulonglong2*)(srcd + i * HDSTR + jb * 8);
        av[i][0] = p.x; av[i][1] = p.y;
    }
    #pragma unroll
    for (int j = 0; j < 2; j++)
        #pragma unroll
        for (int i = 0; i < RPW; i++) {
            fma2(acc[i][0], w[4*j+0], av[i][j]);
            fma2(acc[i][1], w[4*j+1], av[i][j]);
            fma2(acc[i][2], w[4*j+2], av[i][j]);
            fma2(acc[i][3], w[4*j+3], av[i][j]);
        }
    #pragma unroll
    for (int i = 0; i < RPW; i++) {
        const ulonglong2 p = *(const ulonglong2*)(srcd + i * HDSTR + jb * 8 + 4);
        av[i][0] = p.x; av[i][1] = p.y;
    }
    #pragma unroll
    for (int j = 0; j < 2; j++)
        #pragma unroll
        for (int i = 0; i < RPW; i++) {
            fma2(acc[i][0], w[4*(j+2)+0], av[i][j]);
            fma2(acc[i][1], w[4*(j+2)+1], av[i][j]);
            fma2(acc[i][2], w[4*(j+2)+2], av[i][j]);
            fma2(acc[i][3], w[4*(j+2)+3], av[i][j]);
        }
}

// ---- GEMM over duplicated activations, ping-pong weight prefetch (KB even) ----
template<int KB>
__device__ __forceinline__ void gemm_dup(const float* __restrict__ Wg,
                                         const float* __restrict__ srcd,
                                         u64 acc[RPW][4], int c0, int c1)
{
    u64 wA[16], wB[16];
    loadw_u64(wA, Wg, 0, c0, c1);
    #pragma unroll 1
    for (int jb = 0; jb < KB; jb += 2) {
        loadw_u64(wB, Wg, jb + 1, c0, c1);
        fmablock_dup(wA, srcd, jb, acc);
        if (jb + 2 < KB) loadw_u64(wA, Wg, jb + 2, c0, c1);
        fmablock_dup(wB, srcd, jb + 1, acc);
    }
}

// ---- x-GEMM (non-duplicated src, stride XSTR): pk2 movs only here (33 blocks) ----
__device__ __forceinline__ void fmablock_x(const u64 w[16], const float* __restrict__ src,
                                           int jb, u64 acc[RPW][4]) {
    float4 av[RPW];
    #pragma unroll
    for (int i = 0; i < RPW; i++)
        av[i] = *(const float4*)(src + i * XSTR + jb * 4);
    #pragma unroll
    for (int j = 0; j < 4; j++) {
        #pragma unroll
        for (int i = 0; i < RPW; i++) {
            const float v = (j == 0) ? av[i].x : (j == 1) ? av[i].y
                          : (j == 2) ? av[i].z : av[i].w;
            const u64 xv = pk2(v, v);
            fma2(acc[i][0], w[4*j+0], xv);
            fma2(acc[i][1], w[4*j+1], xv);
            fma2(acc[i][2], w[4*j+2], xv);
            fma2(acc[i][3], w[4*j+3], xv);
        }
    }
}

// ---- layer-3: 4 cols/lane, weights g_W3p (stride 132), dup activations ----
__device__ __forceinline__ void loadw3_u64(u64 w[8], int jb, int c0) {
    #pragma unroll
    for (int j = 0; j < 4; j++) {
        const ulonglong2 a = *(const ulonglong2*)(g_W3p + (size_t)(jb * 4 + j) * 132 + c0);
        w[2*j] = a.x; w[2*j+1] = a.y;
    }
}
__device__ __forceinline__ void fmablock3_dup(const u64 w[8], const float* __restrict__ srcd,
                                              int jb, u64 acc[RPW][2]) {
    u64 av[RPW][2];
    #pragma unroll
    for (int i = 0; i < RPW; i++) {
        const ulonglong2 p = *(const ulonglong2*)(srcd + i * HDSTR + jb * 8);
        av[i][0] = p.x; av[i][1] = p.y;
    }
    #pragma unroll
    for (int j = 0; j < 2; j++)
        #pragma unroll
        for (int i = 0; i < RPW; i++) {
            fma2(acc[i][0], w[2*j],   av[i][j]);
            fma2(acc[i][1], w[2*j+1], av[i][j]);
        }
    #pragma unroll
    for (int i = 0; i < RPW; i++) {
        const ulonglong2 p = *(const ulonglong2*)(srcd + i * HDSTR + jb * 8 + 4);
        av[i][0] = p.x; av[i][1] = p.y;
    }
    #pragma unroll
    for (int j = 0; j < 2; j++)
        #pragma unroll
        for (int i = 0; i < RPW; i++) {
            fma2(acc[i][0], w[2*(j+2)],   av[i][j]);
            fma2(acc[i][1], w[2*(j+2)+1], av[i][j]);
        }
}

// LayerNorm (two-pass) + ReLU + store DUPLICATED to smem (stride 512)
__device__ __forceinline__ void ln_relu_store_dup(u64 acc[RPW][4], float* __restrict__ dst,
                                                  const float* __restrict__ g,
                                                  const float* __restrict__ be,
                                                  int c0, int c1)
{
    const float4 ga = *(const float4*)(g + c0);
    const float4 gb = *(const float4*)(g + c1);
    const float4 ba = *(const float4*)(be + c0);
    const float4 bb = *(const float4*)(be + c1);
    #pragma unroll
    for (int i = 0; i < RPW; i++) {
        float2 a0 = up2(acc[i][0]), a1 = up2(acc[i][1]);
        float2 a2 = up2(acc[i][2]), a3 = up2(acc[i][3]);
        float s = ((a0.x + a0.y) + (a1.x + a1.y)) + ((a2.x + a2.y) + (a3.x + a3.y));
        #pragma unroll
        for (int o = 16; o > 0; o >>= 1) s += __shfl_xor_sync(0xffffffffu, s, o);
        const float m = s * (1.0f / 256.0f);
        const float d0 = a0.x - m, d1 = a0.y - m, d2 = a1.x - m, d3 = a1.y - m;
        const float d4 = a2.x - m, d5 = a2.y - m, d6 = a3.x - m, d7 = a3.y - m;
        float ss = ((d0*d0 + d1*d1) + (d2*d2 + d3*d3)) + ((d4*d4 + d5*d5) + (d6*d6 + d7*d7));
        #pragma unroll
        for (int o = 16; o > 0; o >>= 1) ss += __shfl_xor_sync(0xffffffffu, ss, o);
        const float inv = rsqrtf(ss * (1.0f / 256.0f) + EPS_LN);
        const float h0 = fmaxf(d0 * inv * ga.x + ba.x, 0.0f);
        const float h1 = fmaxf(d1 * inv * ga.y + ba.y, 0.0f);
        const float h2 = fmaxf(d2 * inv * ga.z + ba.z, 0.0f);
        const float h3 = fmaxf(d3 * inv * ga.w + ba.w, 0.0f);
        const float h4 = fmaxf(d4 * inv * gb.x + bb.x, 0.0f);
        const float h5 = fmaxf(d5 * inv * gb.y + bb.y, 0.0f);
        const float h6 = fmaxf(d6 * inv * gb.z + bb.z, 0.0f);
        const float h7 = fmaxf(d7 * inv * gb.w + bb.w, 0.0f);
        float4 v;
        v.x = h0; v.y = h0; v.z = h1; v.w = h1;
        *(float4*)(dst + i * HDSTR + 2 * c0) = v;
        v.x = h2; v.y = h2; v.z = h3; v.w = h3;
        *(float4*)(dst + i * HDSTR + 2 * c0 + 4) = v;
        v.x = h4; v.y = h4; v.z = h5; v.w = h5;
        *(float4*)(dst + i * HDSTR + 2 * c1) = v;
        v.x = h6; v.y = h6; v.z = h7; v.w = h7;
        *(float4*)(dst + i * HDSTR + 2 * c1 + 4) = v;
    }
}

// smem: s1 [32][256] + h_dup [32][512] + x [32][132] = 115200 B/CTA (2 CTAs = 225 KB)
#define S1F   (TM * HID)
#define HBDF  (TM * HDSTR)
#define XSF   (TM * XSTR)
#define SMEM_BYTES ((S1F + HBDF + XSF) * sizeof(float))

__global__ void __launch_bounds__(128, 2)
actor_kernel(const float* __restrict__ state,  const float* __restrict__ amask,
             const float* __restrict__ x_init, const float* __restrict__ gumbel,
             const float* __restrict__ W1,     const float* __restrict__ b1,
             const float* __restrict__ g1,     const float* __restrict__ be1,
             const float* __restrict__ W2,     const float* __restrict__ b2,
             const float* __restrict__ g2,     const float* __restrict__ be2,
             const float* __restrict__ b3,     float* __restrict__ out)
{
    extern __shared__ float sm[];
    float* s1  = sm;                    // [TM][256] state@W1a + b1 (step-invariant)
    float* hbd = sm + S1F;              // [TM][512] h buffer, duplicated values
    float* xs  = sm + S1F + HBDF;       // [TM][132] x (129 live + zero pad)

    const int lane  = threadIdx.x & 31;
    const int wid   = threadIdx.x >> 5;
    const int rbase = wid * RPW;
    const size_t grow0 = (size_t)blockIdx.x * TM;
    const int c0 = lane * 4;
    const int c1 = 128 + lane * 4;

    float* xw  = xs  + rbase * XSTR;
    float* hwd = hbd + rbase * HDSTR;
    float* s1w = s1  + rbase * HID;

    // ---- load x rows (stride 129, scalar coalesced) + zero pads ----
    #pragma unroll
    for (int i = 0; i < RPW; i++) {
        const size_t gr = grow0 + rbase + i;
        const float* xp = x_init + gr * ADIM;
        #pragma unroll
        for (int j = 0; j < 4; j++) xw[i * XSTR + lane + 32 * j] = xp[lane + 32 * j];
        if (lane == 0) xw[i * XSTR + 128] = xp[128];
        if (lane >= 1 && lane <= 3) xw[i * XSTR + 128 + lane] = 0.0f;
    }
    // ---- stage state rows DUPLICATED in hbd (for S1 GEMM) ----
    #pragma unroll
    for (int i = 0; i < RPW; i++) {
        const float* sp = state + (grow0 + rbase + i) * SDIM;
        const float4 a = *(const float4*)(sp + c0);
        const float4 b = *(const float4*)(sp + c1);
        float4 v;
        v.x = a.x; v.y = a.x; v.z = a.y; v.w = a.y;
        *(float4*)(hwd + i * HDSTR + 2 * c0) = v;
        v.x = a.z; v.y = a.z; v.z = a.w; v.w = a.w;
        *(float4*)(hwd + i * HDSTR + 2 * c0 + 4) = v;
        v.x = b.x; v.y = b.x; v.z = b.y; v.w = b.y;
        *(float4*)(hwd + i * HDSTR + 2 * c1) = v;
        v.x = b.z; v.y = b.z; v.z = b.w; v.w = b.w;
        *(float4*)(hwd + i * HDSTR + 2 * c1 + 4) = v;
    }
    __syncwarp();

    // step-invariant preloads
    float w128[8];  // W3 col 128, lane-strided over k
    #pragma unroll
    for (int j = 0; j < 8; j++) w128[j] = g_W3p[(size_t)(lane + 32 * j) * 132 + 128];
    const float b3L = __ldg(b3 + 128);

    u64 acc[RPW][4];

    // ---- S1 = state @ W1[0:256,:] + b1 (hoisted) ----
    {
        const float4 ba = *(const float4*)(b1 + c0);
        const float4 bb = *(const float4*)(b1 + c1);
        #pragma unroll
        for (int i = 0; i < RPW; i++) {
            acc[i][0] = pk2(ba.x, ba.y); acc[i][1] = pk2(ba.z, ba.w);
            acc[i][2] = pk2(bb.x, bb.y); acc[i][3] = pk2(bb.z, bb.w);
        }
        gemm_dup<64>(W1, hwd, acc, c0, c1);
        #pragma unroll
        for (int i = 0; i < RPW; i++) {
            float2 a0 = up2(acc[i][0]), a1 = up2(acc[i][1]);
            float2 a2 = up2(acc[i][2]), a3 = up2(acc[i][3]);
            float4 v0; v0.x = a0.x; v0.y = a0.y; v0.z = a1.x; v0.w = a1.y;
            float4 v1; v1.x = a2.x; v1.y = a2.y; v1.z = a3.x; v1.w = a3.y;
            *(float4*)(s1w + i * HID + c0) = v0;
            *(float4*)(s1w + i * HID + c1) = v1;
        }
    }
    __syncwarp();

    // ---- 30 diffusion steps (warp-private, no __syncthreads) ----
    for (int s = 0; s < NSTEP; s++) {
        const float t = (float)(NSTEP - 1 - s);

        // layer 1: acc = S1 + t*W1[385]; += x @ W1x (K=132 padded); LN+ReLU -> hbd
        {
            const float4 wa = *(const float4*)(W1 + (size_t)385 * HID + c0);
            const float4 wb = *(const float4*)(W1 + (size_t)385 * HID + c1);
            #pragma unroll
            for (int i = 0; i < RPW; i++) {
                const float4 sa = *(const float4*)(s1w + i * HID + c0);
                const float4 sb = *(const float4*)(s1w + i * HID + c1);
                acc[i][0] = pk2(fmaf(t, wa.x, sa.x), fmaf(t, wa.y, sa.y));
                acc[i][1] = pk2(fmaf(t, wa.z, sa.z), fmaf(t, wa.w, sa.w));
                acc[i][2] = pk2(fmaf(t, wb.x, sb.x), fmaf(t, wb.y, sb.y));
                acc[i][3] = pk2(fmaf(t, wb.z, sb.z), fmaf(t, wb.w, sb.w));
            }
            // K=33 blocks: 32 in ping-pong + tail
            {
                u64 wA[16], wB[16];
                loadw_u64(wA, g_W1xp, 0, c0, c1);
                #pragma unroll 1
                for (int jb = 0; jb < 32; jb += 2) {
                    loadw_u64(wB, g_W1xp, jb + 1, c0, c1);
                    fmablock_x(wA, xw, jb, acc);
                    loadw_u64(wA, g_W1xp, jb + 2, c0, c1);  // jb+2<=32 valid
                    fmablock_x(wB, xw, jb + 1, acc);
                }
                fmablock_x(wA, xw, 32, acc);                // k=128..131 (zero pad)
            }
            // WAR: hbd (read by prev-step L3 / init staging) now overwritten
            ln_relu_store_dup(acc, hwd, g1, be1, c0, c1);
        }
        __syncwarp();

        // layer 2: acc = b2; += h1 @ W2; LN+ReLU -> hbd
        {
            const float4 ba = *(const float4*)(b2 + c0);
            const float4 bb = *(const float4*)(b2 + c1);
            #pragma unroll
            for (int i = 0; i < RPW; i++) {
                acc[i][0] = pk2(ba.x, ba.y); acc[i][1] = pk2(ba.z, ba.w);
                acc[i][2] = pk2(bb.x, bb.y); acc[i][3] = pk2(bb.z, bb.w);
            }
            gemm_dup<64>(W2, hwd, acc, c0, c1);
            __syncwarp();                      // WAR: all lanes done reading hbd
            ln_relu_store_dup(acc, hwd, g2, be2, c0, c1);
        }
        __syncwarp();

        // layer 3: noise = h2 @ W3 + b3; x -= 0.1*noise
        {
            u64 a3[RPW][2];
            const float4 b3v = *(const float4*)(b3 + c0);
            #pragma unroll
            for (int i = 0; i < RPW; i++) {
                a3[i][0] = pk2(b3v.x, b3v.y);
                a3[i][1] = pk2(b3v.z, b3v.w);
            }
            {
                u64 wA[8], wB[8];
                loadw3_u64(wA, 0, c0);
                #pragma unroll 1
                for (int jb = 0; jb < 64; jb += 2) {
                    loadw3_u64(wB, jb + 1, c0);
                    fmablock3_dup(wA, hwd, jb, a3);
                    if (jb + 2 < 64) loadw3_u64(wA, jb + 2, c0);
                    fmablock3_dup(wB, hwd, jb + 1, a3);
                }
            }
            // col 128: lane-strided partial dot (dup-indexed) + butterfly reduce
            float a128[RPW];
            #pragma unroll
            for (int i = 0; i < RPW; i++) a128[i] = 0.0f;
            #pragma unroll
            for (int j = 0; j < 8; j++) {
                #pragma unroll
                for (int i = 0; i < RPW; i++) {
                    const float hv = hwd[i * HDSTR + 2 * (lane + 32 * j)];
                    a128[i] = fmaf(hv, w128[j], a128[i]);
                }
            }
            #pragma unroll
            for (int i = 0; i < RPW; i++) {
                #pragma unroll
                for (int o = 16; o > 0; o >>= 1)
                    a128[i] += __shfl_xor_sync(0xffffffffu, a128[i], o);
            }
            // x update
            #pragma unroll
            for (int i = 0; i < RPW; i++) {
                float4 xo = *(float4*)(xw + i * XSTR + c0);
                const float2 n0 = up2(a3[i][0]), n1 = up2(a3[i][1]);
                xo.x -= 0.1f * n0.x;
                xo.y -= 0.1f * n0.y;
                xo.z -= 0.1f * n1.x;
                xo.w -= 0.1f * n1.y;
                *(float4*)(xw + i * XSTR + c0) = xo;
                if (lane == 0)
                    xw[i * XSTR + 128] -= 0.1f * (b3L + a128[i]);
            }
        }
        __syncwarp();
    }

    // ---- epilogue: masked gumbel softmax argmax (straight-through) + tanh ----
    #pragma unroll
    for (int i = 0; i < RPW; i++) {
        const size_t gr = grow0 + rbase + i;
        const float4 xv = *(const float4*)(xw + i * XSTR + c0);
        const float4 mk = *(const float4*)(amask  + gr * 128 + c0);
        const float4 gn = *(const float4*)(gumbel + gr * 128 + c0);
        float z[4];
        z[0] = xv.x + (1.0f - mk.x) * (-1e9f) + gn.x;
        z[1] = xv.y + (1.0f - mk.y) * (-1e9f) + gn.y;
        z[2] = xv.z + (1.0f - mk.z) * (-1e9f) + gn.z;
        z[3] = xv.w + (1.0f - mk.w) * (-1e9f) + gn.w;
        float best = z[0]; int bi = c0;
        #pragma unroll
        for (int j = 1; j < 4; j++) if (z[j] > best) { best = z[j]; bi = c0 + j; }
        #pragma unroll
        for (int o = 16; o > 0; o >>= 1) {
            float ov = __shfl_xor_sync(0xffffffffu, best, o);
            int   oi = __shfl_xor_sync(0xffffffffu, bi,   o);
            if (ov > best || (ov == best && oi < bi)) { best = ov; bi = oi; }
        }
        float e[4]; float sl = 0.0f;
        #pragma unroll
        for (int j = 0; j < 4; j++) { e[j] = expf(z[j] - best); sl += e[j]; }
        #pragma unroll
        for (int o = 16; o > 0; o >>= 1) sl += __shfl_xor_sync(0xffffffffu, sl, o);
        #pragma unroll
        for (int j = 0; j < 4; j++) {
            const float p  = e[j] / sl;
            const float yh = (c0 + j == bi) ? 1.0f : 0.0f;
            const float tv = yh + p;
            out[gr * ADIM + c0 + j] = tv - p;
        }
        if (lane == 0) out[gr * ADIM + 128] = tanhf(xw[i * XSTR + 128]);
    }
}

extern "C" void kernel_launch(void* const* d_in, const int* in_sizes, int n_in,
                              void* d_out, int out_size)
{
    const float* state  = (const float*)d_in[0];
    const float* amask  = (const float*)d_in[1];
    const float* x_init = (const float*)d_in[2];
    const float* gumbel = (const float*)d_in[3];
    const float* W1     = (const float*)d_in[4];
    const float* b1     = (const float*)d_in[5];
    const float* g1     = (const float*)d_in[6];
    const float* be1    = (const float*)d_in[7];
    const float* W2     = (const float*)d_in[8];
    const float* b2     = (const float*)d_in[9];
    const float* g2     = (const float*)d_in[10];
    const float* be2    = (const float*)d_in[11];
    const float* W3     = (const float*)d_in[12];
    const float* b3     = (const float*)d_in[13];
    float* out          = (float*)d_out;

    pack_kernel<<<(132 * HID + 255) / 256, 256>>>(W1, W3);

    cudaFuncSetAttribute(actor_kernel,
                         cudaFuncAttributeMaxDynamicSharedMemorySize,
                         (int)SMEM_BYTES);

    actor_kernel<<<NROWS / TM, 128, SMEM_BYTES>>>(
        state, amask, x_init, gumbel,
        W1, b1, g1, be1, W2, b2, g2, be2, b3, out);
}

// round 6
// speedup vs baseline: 1.3624x; 1.0723x over previous
#include <cuda_runtime.h>
#include <cstdint>
#include <math.h>

// ---------------- problem constants ----------------
#define NROWS   65536
#define SDIM    256
#define ADIM    129
#define HID     256
#define NSTEP   30
#define EPS_LN  1e-5f

#define TM      32      // rows per CTA
#define RPW     8       // rows per warp (4 warps * 8 = 32)
#define XSTR    132     // padded float stride for x rows

typedef unsigned long long u64;

// packed fp32x2 helpers (sm_103a FFMA2)
__device__ __forceinline__ u64 pk2(float lo, float hi) {
    u64 r; asm("mov.b64 %0,{%1,%2};" : "=l"(r) : "f"(lo), "f"(hi)); return r;
}
__device__ __forceinline__ float2 up2(u64 v) {
    float lo, hi; asm("mov.b64 {%0,%1},%2;" : "=f"(lo), "=f"(hi) : "l"(v));
    float2 f; f.x = lo; f.y = hi; return f;
}
__device__ __forceinline__ void fma2(u64 &d, u64 a, u64 b) {
    asm("fma.rn.f32x2 %0,%1,%2,%0;" : "+l"(d) : "l"(a), "l"(b));
}

// W1 x-part (rows 256..384) zero-padded to 132 k-rows, stride 256
__device__ float g_W1xp[132 * HID];
// W3 zero-padded to 132 cols, stride 132
__device__ float g_W3p[HID * 132];

__global__ void pack_kernel(const float* __restrict__ W1, const float* __restrict__ W3) {
    int i = blockIdx.x * blockDim.x + threadIdx.x;
    if (i < 132 * HID) {
        int k = i / HID, c = i - k * HID;
        g_W1xp[i] = (k < 129) ? W1[(size_t)(SDIM + k) * HID + c] : 0.0f;
    }
    if (i < HID * 132) {
        int k = i / 132, c = i - k * 132;
        g_W3p[i] = (c < ADIM) ? W3[k * ADIM + c] : 0.0f;
    }
}

// ---- weights: one 4-k block (256-wide row) as u64 halves, accumulator-ready ----
__device__ __forceinline__ void loadw_u64(u64 w[16], const float* __restrict__ Wg,
                                          int jb, int c0, int c1) {
    #pragma unroll
    for (int j = 0; j < 4; j++) {
        const float* p = Wg + (size_t)(jb * 4 + j) * HID;
        const ulonglong2 a = *(const ulonglong2*)(p + c0);
        const ulonglong2 b = *(const ulonglong2*)(p + c1);
        w[4*j+0] = a.x; w[4*j+1] = a.y; w[4*j+2] = b.x; w[4*j+3] = b.y;
    }
}

// ---- activations: one 4-k block for 8 rows (broadcast LDS.128) ----
__device__ __forceinline__ void loadav(float4 av[RPW], const float* __restrict__ src,
                                       int sstr, int jb) {
    #pragma unroll
    for (int i = 0; i < RPW; i++)
        av[i] = *(const float4*)(src + i * sstr + jb * 4);
}

// ---- FMA one 4-k block from prefetched registers ----
__device__ __forceinline__ void fmablock(const u64 w[16], const float4 av[RPW],
                                         u64 acc[RPW][4]) {
    #pragma unroll
    for (int j = 0; j < 4; j++) {
        #pragma unroll
        for (int i = 0; i < RPW; i++) {
            const float v = (j == 0) ? av[i].x : (j == 1) ? av[i].y
                          : (j == 2) ? av[i].z : av[i].w;
            const u64 xv = pk2(v, v);
            fma2(acc[i][0], w[4*j+0], xv);
            fma2(acc[i][1], w[4*j+1], xv);
            fma2(acc[i][2], w[4*j+2], xv);
            fma2(acc[i][3], w[4*j+3], xv);
        }
    }
}

// ---- GEMM: double-buffered weight AND activation prefetch ----
template<int KB>
__device__ __forceinline__ void gemm_pf(const float* __restrict__ Wg,
                                        const float* __restrict__ src, int sstr,
                                        u64 acc[RPW][4], int c0, int c1)
{
    u64 wA[16], wB[16];
    float4 aA[RPW], aB[RPW];
    loadw_u64(wA, Wg, 0, c0, c1);
    loadav(aA, src, sstr, 0);
    #pragma unroll 1
    for (int jb = 0; jb < KB - 1; jb += 2) {
        loadw_u64(wB, Wg, jb + 1, c0, c1);
        loadav(aB, src, sstr, jb + 1);
        fmablock(wA, aA, acc);
        if (jb + 2 < KB) {
            loadw_u64(wA, Wg, jb + 2, c0, c1);
            loadav(aA, src, sstr, jb + 2);
        }
        fmablock(wB, aB, acc);
    }
    if (KB & 1) fmablock(wA, aA, acc);   // tail block (already prefetched)
}

// ---- layer-3 variant: 4 cols/lane, weights g_W3p (stride 132) ----
__device__ __forceinline__ void loadw3_u64(u64 w[8], int jb, int c0) {
    #pragma unroll
    for (int j = 0; j < 4; j++) {
        const ulonglong2 a = *(const ulonglong2*)(g_W3p + (size_t)(jb * 4 + j) * 132 + c0);
        w[2*j] = a.x; w[2*j+1] = a.y;
    }
}
__device__ __forceinline__ void fmablock3(const u64 w[8], const float4 av[RPW],
                                          u64 acc[RPW][2]) {
    #pragma unroll
    for (int j = 0; j < 4; j++) {
        #pragma unroll
        for (int i = 0; i < RPW; i++) {
            const float v = (j == 0) ? av[i].x : (j == 1) ? av[i].y
                          : (j == 2) ? av[i].z : av[i].w;
            const u64 xv = pk2(v, v);
            fma2(acc[i][0], w[2*j],   xv);
            fma2(acc[i][1], w[2*j+1], xv);
        }
    }
}

// LayerNorm (two-pass) + ReLU + store to smem (stride 256)
__device__ __forceinline__ void ln_relu_store(u64 acc[RPW][4], float* __restrict__ dst,
                                              const float* __restrict__ g,
                                              const float* __restrict__ be,
                                              int c0, int c1)
{
    const float4 ga = *(const float4*)(g + c0);
    const float4 gb = *(const float4*)(g + c1);
    const float4 ba = *(const float4*)(be + c0);
    const float4 bb = *(const float4*)(be + c1);
    #pragma unroll
    for (int i = 0; i < RPW; i++) {
        float2 a0 = up2(acc[i][0]), a1 = up2(acc[i][1]);
        float2 a2 = up2(acc[i][2]), a3 = up2(acc[i][3]);
        float s = ((a0.x + a0.y) + (a1.x + a1.y)) + ((a2.x + a2.y) + (a3.x + a3.y));
        #pragma unroll
        for (int o = 16; o > 0; o >>= 1) s += __shfl_xor_sync(0xffffffffu, s, o);
        const float m = s * (1.0f / 256.0f);
        const float d0 = a0.x - m, d1 = a0.y - m, d2 = a1.x - m, d3 = a1.y - m;
        const float d4 = a2.x - m, d5 = a2.y - m, d6 = a3.x - m, d7 = a3.y - m;
        float ss = ((d0*d0 + d1*d1) + (d2*d2 + d3*d3)) + ((d4*d4 + d5*d5) + (d6*d6 + d7*d7));
        #pragma unroll
        for (int o = 16; o > 0; o >>= 1) ss += __shfl_xor_sync(0xffffffffu, ss, o);
        const float inv = rsqrtf(ss * (1.0f / 256.0f) + EPS_LN);
        float4 h0, h1;
        h0.x = fmaxf(d0 * inv * ga.x + ba.x, 0.0f);
        h0.y = fmaxf(d1 * inv * ga.y + ba.y, 0.0f);
        h0.z = fmaxf(d2 * inv * ga.z + ba.z, 0.0f);
        h0.w = fmaxf(d3 * inv * ga.w + ba.w, 0.0f);
        h1.x = fmaxf(d4 * inv * gb.x + bb.x, 0.0f);
        h1.y = fmaxf(d5 * inv * gb.y + bb.y, 0.0f);
        h1.z = fmaxf(d6 * inv * gb.z + bb.z, 0.0f);
        h1.w = fmaxf(d7 * inv * gb.w + bb.w, 0.0f);
        *(float4*)(dst + i * HID + c0) = h0;
        *(float4*)(dst + i * HID + c1) = h1;
    }
}

// smem: s1 [32][256] + h [32][256] + x [32][132] = 82432 B/CTA -> 2 CTAs/SM
#define S1F   (TM * HID)
#define HBF   (TM * HID)
#define XSF   (TM * XSTR)
#define SMEM_BYTES ((S1F + HBF + XSF) * sizeof(float))

__global__ void __launch_bounds__(128, 2)
actor_kernel(const float* __restrict__ state,  const float* __restrict__ amask,
             const float* __restrict__ x_init, const float* __restrict__ gumbel,
             const float* __restrict__ W1,     const float* __restrict__ b1,
             const float* __restrict__ g1,     const float* __restrict__ be1,
             const float* __restrict__ W2,     const float* __restrict__ b2,
             const float* __restrict__ g2,     const float* __restrict__ be2,
             const float* __restrict__ b3,     float* __restrict__ out)
{
    extern __shared__ float sm[];
    float* s1 = sm;                    // [TM][256] state@W1a + b1 (step-invariant)
    float* hb = sm + S1F;              // [TM][256] h buffer
    float* xs = sm + S1F + HBF;        // [TM][132] x (129 live + zero pad)

    const int lane  = threadIdx.x & 31;
    const int wid   = threadIdx.x >> 5;
    const int rbase = wid * RPW;
    const size_t grow0 = (size_t)blockIdx.x * TM;
    const int c0 = lane * 4;
    const int c1 = 128 + lane * 4;

    float* xw  = xs + rbase * XSTR;
    float* hw  = hb + rbase * HID;
    float* s1w = s1 + rbase * HID;

    // ---- load x rows (stride 129, scalar coalesced) + zero pads ----
    #pragma unroll
    for (int i = 0; i < RPW; i++) {
        const size_t gr = grow0 + rbase + i;
        const float* xp = x_init + gr * ADIM;
        #pragma unroll
        for (int j = 0; j < 4; j++) xw[i * XSTR + lane + 32 * j] = xp[lane + 32 * j];
        if (lane == 0) xw[i * XSTR + 128] = xp[128];
        if (lane >= 1 && lane <= 3) xw[i * XSTR + 128 + lane] = 0.0f;
    }
    // ---- stage state rows in hb ----
    #pragma unroll
    for (int i = 0; i < RPW; i++) {
        const float* sp = state + (grow0 + rbase + i) * SDIM;
        *(float4*)(hw + i * HID + c0) = *(const float4*)(sp + c0);
        *(float4*)(hw + i * HID + c1) = *(const float4*)(sp + c1);
    }
    __syncwarp();

    // step-invariant preloads
    float w128[8];  // W3 col 128, lane-strided over k
    #pragma unroll
    for (int j = 0; j < 8; j++) w128[j] = g_W3p[(size_t)(lane + 32 * j) * 132 + 128];
    const float b3L = __ldg(b3 + 128);

    u64 acc[RPW][4];

    // ---- S1 = state @ W1[0:256,:] + b1 (hoisted) ----
    {
        const float4 ba = *(const float4*)(b1 + c0);
        const float4 bb = *(const float4*)(b1 + c1);
        #pragma unroll
        for (int i = 0; i < RPW; i++) {
            acc[i][0] = pk2(ba.x, ba.y); acc[i][1] = pk2(ba.z, ba.w);
            acc[i][2] = pk2(bb.x, bb.y); acc[i][3] = pk2(bb.z, bb.w);
        }
        gemm_pf<64>(W1, hw, HID, acc, c0, c1);
        #pragma unroll
        for (int i = 0; i < RPW; i++) {
            float2 a0 = up2(acc[i][0]), a1 = up2(acc[i][1]);
            float2 a2 = up2(acc[i][2]), a3 = up2(acc[i][3]);
            float4 v0; v0.x = a0.x; v0.y = a0.y; v0.z = a1.x; v0.w = a1.y;
            float4 v1; v1.x = a2.x; v1.y = a2.y; v1.z = a3.x; v1.w = a3.y;
            *(float4*)(s1w + i * HID + c0) = v0;
            *(float4*)(s1w + i * HID + c1) = v1;
        }
    }
    __syncwarp();

    // ---- 30 diffusion steps (warp-private, no __syncthreads) ----
    for (int s = 0; s < NSTEP; s++) {
        const float t = (float)(NSTEP - 1 - s);

        // layer 1: acc = S1 + t*W1[385]; += x @ W1x (K=132 padded); LN+ReLU -> hb
        {
            const float4 wa = *(const float4*)(W1 + (size_t)385 * HID + c0);
            const float4 wb = *(const float4*)(W1 + (size_t)385 * HID + c1);
            #pragma unroll
            for (int i = 0; i < RPW; i++) {
                const float4 sa = *(const float4*)(s1w + i * HID + c0);
                const float4 sb = *(const float4*)(s1w + i * HID + c1);
                acc[i][0] = pk2(fmaf(t, wa.x, sa.x), fmaf(t, wa.y, sa.y));
                acc[i][1] = pk2(fmaf(t, wa.z, sa.z), fmaf(t, wa.w, sa.w));
                acc[i][2] = pk2(fmaf(t, wb.x, sb.x), fmaf(t, wb.y, sb.y));
                acc[i][3] = pk2(fmaf(t, wb.z, sb.z), fmaf(t, wb.w, sb.w));
            }
            gemm_pf<33>(g_W1xp, xw, XSTR, acc, c0, c1);
            ln_relu_store(acc, hw, g1, be1, c0, c1);
        }
        __syncwarp();

        // layer 2: acc = b2; += h1 @ W2; LN+ReLU -> hb
        {
            const float4 ba = *(const float4*)(b2 + c0);
            const float4 bb = *(const float4*)(b2 + c1);
            #pragma unroll
            for (int i = 0; i < RPW; i++) {
                acc[i][0] = pk2(ba.x, ba.y); acc[i][1] = pk2(ba.z, ba.w);
                acc[i][2] = pk2(bb.x, bb.y); acc[i][3] = pk2(bb.z, bb.w);
            }
            gemm_pf<64>(W2, hw, HID, acc, c0, c1);
            __syncwarp();                      // WAR: all lanes done reading hb
            ln_relu_store(acc, hw, g2, be2, c0, c1);
        }
        __syncwarp();

        // layer 3: noise = h2 @ W3 + b3; x -= 0.1*noise
        {
            u64 a3[RPW][2];
            const float4 b3v = *(const float4*)(b3 + c0);
            #pragma unroll
            for (int i = 0; i < RPW; i++) {
                a3[i][0] = pk2(b3v.x, b3v.y);
                a3[i][1] = pk2(b3v.z, b3v.w);
            }
            // main 128 cols (4 per lane), double-buffered weights + acts
            {
                u64 wA[8], wB[8];
                float4 aA[RPW], aB[RPW];
                loadw3_u64(wA, 0, c0);
                loadav(aA, hw, HID, 0);
                #pragma unroll 1
                for (int jb = 0; jb < 64; jb += 2) {
                    loadw3_u64(wB, jb + 1, c0);
                    loadav(aB, hw, HID, jb + 1);
                    fmablock3(wA, aA, a3);
                    if (jb + 2 < 64) {
                        loadw3_u64(wA, jb + 2, c0);
                        loadav(aA, hw, HID, jb + 2);
                    }
                    fmablock3(wB, aB, a3);
                }
            }
            // col 128: lane-strided partial dot + butterfly reduce per row
            float a128[RPW];
            #pragma unroll
            for (int i = 0; i < RPW; i++) a128[i] = 0.0f;
            #pragma unroll
            for (int j = 0; j < 8; j++) {
                #pragma unroll
                for (int i = 0; i < RPW; i++) {
                    const float hv = hw[i * HID + lane + 32 * j];
                    a128[i] = fmaf(hv, w128[j], a128[i]);
                }
            }
            #pragma unroll
            for (int i = 0; i < RPW; i++) {
                #pragma unroll
                for (int o = 16; o > 0; o >>= 1)
                    a128[i] += __shfl_xor_sync(0xffffffffu, a128[i], o);
            }
            // x update
            #pragma unroll
            for (int i = 0; i < RPW; i++) {
                float4 xo = *(float4*)(xw + i * XSTR + c0);
                const float2 n0 = up2(a3[i][0]), n1 = up2(a3[i][1]);
                xo.x -= 0.1f * n0.x;
                xo.y -= 0.1f * n0.y;
                xo.z -= 0.1f * n1.x;
                xo.w -= 0.1f * n1.y;
                *(float4*)(xw + i * XSTR + c0) = xo;
                if (lane == 0)
                    xw[i * XSTR + 128] -= 0.1f * (b3L + a128[i]);
            }
        }
        __syncwarp();
    }

    // ---- epilogue: masked gumbel softmax argmax (straight-through) + tanh ----
    #pragma unroll
    for (int i = 0; i < RPW; i++) {
        const size_t gr = grow0 + rbase + i;
        const float4 xv = *(const float4*)(xw + i * XSTR + c0);
        const float4 mk = *(const float4*)(amask  + gr * 128 + c0);
        const float4 gn = *(const float4*)(gumbel + gr * 128 + c0);
        float z[4];
        z[0] = xv.x + (1.0f - mk.x) * (-1e9f) + gn.x;
        z[1] = xv.y + (1.0f - mk.y) * (-1e9f) + gn.y;
        z[2] = xv.z + (1.0f - mk.z) * (-1e9f) + gn.z;
        z[3] = xv.w + (1.0f - mk.w) * (-1e9f) + gn.w;
        float best = z[0]; int bi = c0;
        #pragma unroll
        for (int j = 1; j < 4; j++) if (z[j] > best) { best = z[j]; bi = c0 + j; }
        #pragma unroll
        for (int o = 16; o > 0; o >>= 1) {
            float ov = __shfl_xor_sync(0xffffffffu, best, o);
            int   oi = __shfl_xor_sync(0xffffffffu, bi,   o);
            if (ov > best || (ov == best && oi < bi)) { best = ov; bi = oi; }
        }
        float e[4]; float sl = 0.0f;
        #pragma unroll
        for (int j = 0; j < 4; j++) { e[j] = expf(z[j] - best); sl += e[j]; }
        #pragma unroll
        for (int o = 16; o > 0; o >>= 1) sl += __shfl_xor_sync(0xffffffffu, sl, o);
        #pragma unroll
        for (int j = 0; j < 4; j++) {
            const float p  = e[j] / sl;
            const float yh = (c0 + j == bi) ? 1.0f : 0.0f;
            const float tv = yh + p;
            out[gr * ADIM + c0 + j] = tv - p;
        }
        if (lane == 0) out[gr * ADIM + 128] = tanhf(xw[i * XSTR + 128]);
    }
}

extern "C" void kernel_launch(void* const* d_in, const int* in_sizes, int n_in,
                              void* d_out, int out_size)
{
    const float* state  = (const float*)d_in[0];
    const float* amask  = (const float*)d_in[1];
    const float* x_init = (const float*)d_in[2];
    const float* gumbel = (const float*)d_in[3];
    const float* W1     = (const float*)d_in[4];
    const float* b1     = (const float*)d_in[5];
    const float* g1     = (const float*)d_in[6];
    const float* be1    = (const float*)d_in[7];
    const float* W2     = (const float*)d_in[8];
    const float* b2     = (const float*)d_in[9];
    const float* g2     = (const float*)d_in[10];
    const float* be2    = (const float*)d_in[11];
    const float* W3     = (const float*)d_in[12];
    const float* b3     = (const float*)d_in[13];
    float* out          = (float*)d_out;

    pack_kernel<<<(132 * HID + 255) / 256, 256>>>(W1, W3);

    cudaFuncSetAttribute(actor_kernel,
                         cudaFuncAttributeMaxDynamicSharedMemorySize,
                         (int)SMEM_BYTES);

    actor_kernel<<<NROWS / TM, 128, SMEM_BYTES>>>(
        state, amask, x_init, gumbel,
        W1, b1, g1, be1, W2, b2, g2, be2, b3, out);
}